// round 2
// baseline (speedup 1.0000x reference)
#include <cuda_runtime.h>
#include <math.h>

#define TTOK 36864   // 4096 batches * 9 spatial

// Scratch (device globals; allocation-free per harness rules)
__device__ float g_big[56623104];   // [1536][T]: rows 0-511 x^T, 512-1023 o3_att, 1024-1535 o7_att
__device__ float g_act[18874368];   // [512][T]: o3^T, then reused for o7^T
__device__ float g_qkv[56623104];   // [1536][T]: q | k | v
__device__ float g_mean[1536];
__device__ float g_var[1536];
__device__ float g_scale[1536];
__device__ float g_shift[1536];

// ---------------------------------------------------------------------------
// x [B, 512, 9] -> g_big rows [0,512) as [C, T], T token = b*9+hw
// ---------------------------------------------------------------------------
__global__ void transpose_in_kernel(const float* __restrict__ x) {
    __shared__ float s[32][296];          // [c][b*9+hw], padded
    int c0 = blockIdx.x * 32;
    int b0 = blockIdx.y * 32;
    int tid = threadIdx.x;                // 0..287 = (c_local*9 + hw)
    const float* xp = x + (size_t)b0 * 4608 + (size_t)c0 * 9;
#pragma unroll 4
    for (int b = 0; b < 32; b++) {
        s[tid / 9][b * 9 + tid % 9] = xp[(size_t)b * 4608 + tid];
    }
    __syncthreads();
#pragma unroll 4
    for (int c = 0; c < 32; c++) {
        g_big[(size_t)(c0 + c) * TTOK + b0 * 9 + tid] = s[c][tid];
    }
}

// ---------------------------------------------------------------------------
// Per-channel mean/var (biased) over a row of g_big
// ---------------------------------------------------------------------------
__global__ void stats_kernel(int rowOff) {
    int c = blockIdx.x + rowOff;
    const float* row = g_big + (size_t)c * TTOK;
    float s = 0.f, q = 0.f;
    for (int t = threadIdx.x; t < TTOK; t += 256) {
        float v = row[t];
        s += v;
        q += v * v;
    }
    __shared__ float rs[256], rq[256];
    rs[threadIdx.x] = s; rq[threadIdx.x] = q;
    __syncthreads();
    for (int o = 128; o > 0; o >>= 1) {
        if (threadIdx.x < o) {
            rs[threadIdx.x] += rs[threadIdx.x + o];
            rq[threadIdx.x] += rq[threadIdx.x + o];
        }
        __syncthreads();
    }
    if (threadIdx.x == 0) {
        float m = rs[0] / (float)TTOK;
        g_mean[c] = m;
        g_var[c]  = rq[0] / (float)TTOK - m * m;
    }
}

// Fold BN (gamma, beta, mean, var) into y = x*scale + shift
__global__ void scaleshift_kernel(const float* __restrict__ gam,
                                  const float* __restrict__ bet, int n) {
    int i = blockIdx.x * blockDim.x + threadIdx.x;
    if (i < n) {
        float inv = rsqrtf(g_var[i] + 1e-5f);
        float sc  = gam[i] * inv;
        g_scale[i] = sc;
        g_shift[i] = bet[i] - g_mean[i] * sc;
    }
}

// ---------------------------------------------------------------------------
// out[m,t] = sum_k act(A[k,t]) * W[m,k] + bias[m]
// act = relu(v*scale[k]+shift[k]) if ACT.  A: [K,T], W: [M,K] row-major.
// 128x128x16 tiles, 256 threads, 8x8 microtile (strided, conflict-free LDS).
// ---------------------------------------------------------------------------
template<bool ACT, bool TRANSOUT>
__global__ __launch_bounds__(256, 2)
void gemm_kernel(const float* __restrict__ A, const float* __restrict__ W,
                 const float* __restrict__ bias, float* __restrict__ out, int K) {
    __shared__ float As[16][128];
    __shared__ float Ws[16][129];
    const int tid = threadIdx.x;
    const int bn = blockIdx.x * 128;
    const int bm = blockIdx.y * 128;
    const int tc = tid & 15;   // column group
    const int tr = tid >> 4;   // row group
    float acc[8][8] = {};

    for (int k0 = 0; k0 < K; k0 += 16) {
#pragma unroll
        for (int i = 0; i < 8; i++) {
            int lin = tid + i * 256;
            int kk = lin >> 7, nn = lin & 127;
            float v = A[(size_t)(k0 + kk) * TTOK + bn + nn];
            if (ACT) v = fmaxf(fmaf(v, g_scale[k0 + kk], g_shift[k0 + kk]), 0.f);
            As[kk][nn] = v;
        }
#pragma unroll
        for (int i = 0; i < 8; i++) {
            int lin = tid + i * 256;
            int mm = lin >> 4, kk = lin & 15;
            Ws[kk][mm] = W[(size_t)(bm + mm) * K + k0 + kk];
        }
        __syncthreads();
#pragma unroll
        for (int kk = 0; kk < 16; kk++) {
            float a[8], w[8];
#pragma unroll
            for (int j = 0; j < 8; j++) a[j] = As[kk][tc + 16 * j];
#pragma unroll
            for (int i = 0; i < 8; i++) w[i] = Ws[kk][tr + 16 * i];
#pragma unroll
            for (int i = 0; i < 8; i++)
#pragma unroll
                for (int j = 0; j < 8; j++)
                    acc[i][j] = fmaf(w[i], a[j], acc[i][j]);
        }
        __syncthreads();
    }

#pragma unroll
    for (int i = 0; i < 8; i++) {
        int m = bm + tr + 16 * i;
        float bv = bias[m];
#pragma unroll
        for (int j = 0; j < 8; j++) {
            int t = bn + tc + 16 * j;
            float v = acc[i][j] + bv;
            if (TRANSOUT) {
                int b = t / 9, hw = t - b * 9;
                out[((size_t)b * 512 + m) * 9 + hw] = v;   // [B, 512, 3, 3]
            } else {
                out[(size_t)m * TTOK + t] = v;
            }
        }
    }
}

// ---------------------------------------------------------------------------
// MHSA core. One block per (batch, head). q/k/v: g_qkv rows [0|512|1024)+h*128.
// L[n,m] = sum_d q[d,n]k[d,m] + pos[d,n]q[d,m]; softmax over m; out = attn @ v^T
// ---------------------------------------------------------------------------
__global__ void attn_kernel(const float* __restrict__ relh,
                            const float* __restrict__ relw, int outRowOff) {
    int b = blockIdx.x >> 2;
    int h = blockIdx.x & 3;
    int d = threadIdx.x;                    // 0..127
    __shared__ float sq[128][9], sk[128][9], sv[128][9], sp[128][9];
    __shared__ float sl[9][9];
    int row = h * 128 + d;
    size_t tb = (size_t)b * 9;
    const float* qp = g_qkv + (size_t)row * TTOK + tb;
    const float* kp = g_qkv + (size_t)(512 + row) * TTOK + tb;
    const float* vp = g_qkv + (size_t)(1024 + row) * TTOK + tb;
#pragma unroll
    for (int m = 0; m < 9; m++) {
        sq[d][m] = qp[m];
        sk[d][m] = kp[m];
        sv[d][m] = vp[m];
    }
    float rw[3], rh[3];
#pragma unroll
    for (int i = 0; i < 3; i++) { rw[i] = relw[row * 3 + i]; rh[i] = relh[row * 3 + i]; }
#pragma unroll
    for (int i = 0; i < 3; i++)
#pragma unroll
        for (int j = 0; j < 3; j++)
            sp[d][i * 3 + j] = rw[i] + rh[j];   // pos[h,d,n], n = i*3+j
    __syncthreads();

    if (d < 81) {
        int n = d / 9, m = d % 9;
        float acc = 0.f;
#pragma unroll 4
        for (int dd = 0; dd < 128; dd++)
            acc += sq[dd][n] * sk[dd][m] + sp[dd][n] * sq[dd][m];
        sl[n][m] = acc;
    }
    __syncthreads();
    if (d < 9) {
        float mx = sl[d][0];
#pragma unroll
        for (int m = 1; m < 9; m++) mx = fmaxf(mx, sl[d][m]);
        float e[9], sum = 0.f;
#pragma unroll
        for (int m = 0; m < 9; m++) { e[m] = __expf(sl[d][m] - mx); sum += e[m]; }
        float inv = 1.f / sum;
#pragma unroll
        for (int m = 0; m < 9; m++) sl[d][m] = e[m] * inv;
    }
    __syncthreads();
    float* op = g_big + (size_t)(outRowOff + row) * TTOK + tb;
#pragma unroll
    for (int n = 0; n < 9; n++) {
        float acc = 0.f;
#pragma unroll
        for (int m = 0; m < 9; m++) acc = fmaf(sv[d][m], sl[n][m], acc);
        op[n] = acc;
    }
}

// ---------------------------------------------------------------------------
extern "C" void kernel_launch(void* const* d_in, const int* in_sizes, int n_in,
                              void* d_out, int out_size) {
    const float* x     = (const float*)d_in[0];
    const float* bn1_g = (const float*)d_in[1];
    const float* bn1_b = (const float*)d_in[2];
    const float* w1    = (const float*)d_in[3];
    const float* b1    = (const float*)d_in[4];
    const float* q_w   = (const float*)d_in[5];
    const float* q_b   = (const float*)d_in[6];
    const float* k_w   = (const float*)d_in[7];
    const float* k_b   = (const float*)d_in[8];
    const float* v_w   = (const float*)d_in[9];
    const float* v_b   = (const float*)d_in[10];
    const float* rel_h = (const float*)d_in[11];
    const float* rel_w = (const float*)d_in[12];
    const float* bn2_g = (const float*)d_in[13];
    const float* bn2_b = (const float*)d_in[14];
    const float* w2    = (const float*)d_in[15];
    const float* b2    = (const float*)d_in[16];
    const float* bn3_g = (const float*)d_in[17];
    const float* bn3_b = (const float*)d_in[18];
    const float* w3    = (const float*)d_in[19];
    const float* b3    = (const float*)d_in[20];

    float *big, *act, *qkv;
    cudaGetSymbolAddress((void**)&big, g_big);
    cudaGetSymbolAddress((void**)&act, g_act);
    cudaGetSymbolAddress((void**)&qkv, g_qkv);

    dim3 ggrid(TTOK / 128, 4);   // 288 x 4 = 1152 blocks per GEMM

    // x -> channel-major
    transpose_in_kernel<<<dim3(16, 128), 288>>>(x);

    // ---- stage 1: o3 = conv(relu(bn1(x))) ----
    stats_kernel<<<512, 256>>>(0);
    scaleshift_kernel<<<2, 256>>>(bn1_g, bn1_b, 512);
    gemm_kernel<true,  false><<<ggrid, 256>>>(big, w1, b1, act, 512);

    // ---- MHSA(o3) ----
    gemm_kernel<false, false><<<ggrid, 256>>>(act, q_w, q_b, qkv,                      512);
    gemm_kernel<false, false><<<ggrid, 256>>>(act, k_w, k_b, qkv + (size_t)512 * TTOK, 512);
    gemm_kernel<false, false><<<ggrid, 256>>>(act, v_w, v_b, qkv + (size_t)1024 * TTOK, 512);
    attn_kernel<<<4096 * 4, 128>>>(rel_h, rel_w, 512);       // -> big rows [512,1024)

    // ---- stage 2: o7 = conv(relu(bn2(concat[x, o3_att]))) ----
    stats_kernel<<<512, 256>>>(512);
    scaleshift_kernel<<<4, 256>>>(bn2_g, bn2_b, 1024);
    gemm_kernel<true,  false><<<ggrid, 256>>>(big, w2, b2, act, 1024);

    // ---- MHSA(o7) ----
    gemm_kernel<false, false><<<ggrid, 256>>>(act, q_w, q_b, qkv,                      512);
    gemm_kernel<false, false><<<ggrid, 256>>>(act, k_w, k_b, qkv + (size_t)512 * TTOK, 512);
    gemm_kernel<false, false><<<ggrid, 256>>>(act, v_w, v_b, qkv + (size_t)1024 * TTOK, 512);
    attn_kernel<<<4096 * 4, 128>>>(rel_h, rel_w, 1024);      // -> big rows [1024,1536)

    // ---- stage 3: out = conv(relu(bn3(concat[x, o3_att, o7_att]))) ----
    stats_kernel<<<512, 256>>>(1024);
    scaleshift_kernel<<<6, 256>>>(bn3_g, bn3_b, 1536);
    gemm_kernel<true,  true ><<<ggrid, 256>>>(big, w3, b3, (float*)d_out, 1536);
}

// round 4
// speedup vs baseline: 3.1692x; 3.1692x over previous
#include <cuda_runtime.h>
#include <cuda_bf16.h>
#include <cstdint>

#define T_TOK 36864

// ---------------- scratch ----------------
__device__ __align__(16) float g_big[56623104];            // [T][1536] fp32: x | o3_att | o7_att
__device__ __align__(16) float g_qkv[56623104];            // q|k|v each [T][512] fp32
__device__ __align__(16) __nv_bfloat16 g_bh[56623104];     // BN'd stage input hi [T][Ks]
__device__ __align__(16) __nv_bfloat16 g_bl[56623104];     // lo
__device__ __align__(16) __nv_bfloat16 g_ah[18874368];     // o3/o7 hi [T][512]
__device__ __align__(16) __nv_bfloat16 g_al[18874368];     // lo
__device__ __align__(16) __nv_bfloat16 g_wh[786432];       // weight hi [512][K]
__device__ __align__(16) __nv_bfloat16 g_wl[786432];       // lo
__device__ __align__(16) float g_ps[98304];
__device__ __align__(16) float g_pq[98304];
__device__ float g_mean[1536];
__device__ float g_var[1536];
__device__ __align__(16) float g_scale[1536];
__device__ __align__(16) float g_shift[1536];

__device__ __forceinline__ uint32_t smem_u32(const void* p) {
    uint32_t a;
    asm("{ .reg .u64 t; cvta.to.shared.u64 t, %1; cvt.u32.u64 %0, t; }" : "=r"(a) : "l"(p));
    return a;
}
#define LDM4(r, addr)                                                              \
    asm volatile("ldmatrix.sync.aligned.m8n8.x4.shared.b16 {%0,%1,%2,%3}, [%4];"   \
        : "=r"((r)[0]), "=r"((r)[1]), "=r"((r)[2]), "=r"((r)[3]) : "r"(addr))

__device__ __forceinline__ void mma_bf16(float* c, const uint32_t* a, const uint32_t* b) {
    asm volatile("mma.sync.aligned.m16n8k16.row.col.f32.bf16.bf16.f32 "
        "{%0,%1,%2,%3}, {%4,%5,%6,%7}, {%8,%9}, {%0,%1,%2,%3};"
        : "+f"(c[0]), "+f"(c[1]), "+f"(c[2]), "+f"(c[3])
        : "r"(a[0]), "r"(a[1]), "r"(a[2]), "r"(a[3]), "r"(b[0]), "r"(b[1]));
}

// ---------------------------------------------------------------------------
// x [B,512,3,3] -> g_big[t][c] (token-major), cols 0..511
__global__ void transpose_in(const float* __restrict__ x) {
    __shared__ float s[4608];
    const float* xp = x + (size_t)blockIdx.x * 4608;
#pragma unroll
    for (int i = threadIdx.x; i < 4608; i += 512) s[i] = xp[i];
    __syncthreads();
#pragma unroll
    for (int hw = 0; hw < 9; hw++)
        g_big[((size_t)blockIdx.x * 9 + hw) * 1536 + threadIdx.x] = s[threadIdx.x * 9 + hw];
}

__global__ void stats_part(int c0) {
    int c = c0 + threadIdx.x;
    int r0 = blockIdx.x * 576;
    float s = 0.f, q = 0.f;
    for (int r = r0; r < r0 + 576; r++) {
        float v = g_big[(size_t)r * 1536 + c];
        s += v; q += v * v;
    }
    g_ps[blockIdx.x * 1536 + c] = s;
    g_pq[blockIdx.x * 1536 + c] = q;
}
__global__ void stats_fin(int c0) {
    int c = c0 + blockIdx.x * 256 + threadIdx.x;
    float s = 0.f, q = 0.f;
    for (int rb = 0; rb < 64; rb++) { s += g_ps[rb * 1536 + c]; q += g_pq[rb * 1536 + c]; }
    float m = s / (float)T_TOK;
    g_mean[c] = m;
    g_var[c] = q / (float)T_TOK - m * m;
}
__global__ void scaleshift(const float* __restrict__ gam, const float* __restrict__ bet, int n) {
    int i = blockIdx.x * 256 + threadIdx.x;
    if (i < n) {
        float inv = rsqrtf(g_var[i] + 1e-5f);
        float sc = gam[i] * inv;
        g_scale[i] = sc;
        g_shift[i] = bet[i] - g_mean[i] * sc;
    }
}

// ---------------------------------------------------------------------------
// relu(bn(g_big[:, 0:Ks])) -> bf16 hi/lo compact [T][Ks]; 8 elems / thread
__global__ void conv_big(int Ks) {
    uint32_t i8 = ((uint32_t)blockIdx.x * 256u + threadIdx.x) * 8u;
    int t = (int)(i8 / (uint32_t)Ks);
    int c = (int)(i8 % (uint32_t)Ks);
    const float* src = g_big + (size_t)t * 1536 + c;
    float v[8];
    *(float4*)(v)     = *(const float4*)src;
    *(float4*)(v + 4) = *(const float4*)(src + 4);
    float sc[8], sh[8];
    *(float4*)(sc)     = *(const float4*)(g_scale + c);
    *(float4*)(sc + 4) = *(const float4*)(g_scale + c + 4);
    *(float4*)(sh)     = *(const float4*)(g_shift + c);
    *(float4*)(sh + 4) = *(const float4*)(g_shift + c + 4);
    uint4 H, L;
    uint32_t* hp = &H.x;
    uint32_t* lp = &L.x;
#pragma unroll
    for (int i = 0; i < 4; i++) {
        float a = fmaxf(fmaf(v[2 * i], sc[2 * i], sh[2 * i]), 0.f);
        float b = fmaxf(fmaf(v[2 * i + 1], sc[2 * i + 1], sh[2 * i + 1]), 0.f);
        __nv_bfloat162 h = __floats2bfloat162_rn(a, b);
        float2 hf = __bfloat1622float2(h);
        __nv_bfloat162 l = __floats2bfloat162_rn(a - hf.x, b - hf.y);
        hp[i] = *(uint32_t*)&h;
        lp[i] = *(uint32_t*)&l;
    }
    *(uint4*)(g_bh + i8) = H;
    *(uint4*)(g_bl + i8) = L;
}

// weight [512][K] fp32 -> g_wh/g_wl; 8 elems / thread
__global__ void conv_w(const float* __restrict__ w) {
    uint32_t i8 = ((uint32_t)blockIdx.x * 256u + threadIdx.x) * 8u;
    float v[8];
    *(float4*)(v)     = *(const float4*)(w + i8);
    *(float4*)(v + 4) = *(const float4*)(w + i8 + 4);
    uint4 H, L;
    uint32_t* hp = &H.x;
    uint32_t* lp = &L.x;
#pragma unroll
    for (int i = 0; i < 4; i++) {
        __nv_bfloat162 h = __floats2bfloat162_rn(v[2 * i], v[2 * i + 1]);
        float2 hf = __bfloat1622float2(h);
        __nv_bfloat162 l = __floats2bfloat162_rn(v[2 * i] - hf.x, v[2 * i + 1] - hf.y);
        hp[i] = *(uint32_t*)&h;
        lp[i] = *(uint32_t*)&l;
    }
    *(uint4*)(g_wh + i8) = H;
    *(uint4*)(g_wl + i8) = L;
}

// ---------------------------------------------------------------------------
// out[t,m] = sum_k A[t,k]*W[m,k] + bias[m] with bf16x3.
// Block 128 tok x 128 ch, 8 warps (2x4), warp tile 64x32, k16 double-buffered.
// OM: 0 = split-out to g_ah/g_al, 1 = fp32 out [T][512], 2 = fp32 out [B,512,3,3]
#define PITCH 48
#define BUFSZ 24576   // Ah 6144 | Al 6144 | Wh 6144 | Wl 6144
template<int OM>
__global__ __launch_bounds__(256)
void mma_gemm(const __nv_bfloat16* __restrict__ Ah, const __nv_bfloat16* __restrict__ Al,
              const int K, const float* __restrict__ bias, float* __restrict__ out) {
    extern __shared__ char smem[];
    const uint32_t sb = smem_u32(smem);
    const int tid = threadIdx.x;
    const int wid = tid >> 5, lane = tid & 31;
    const int warp_m = wid & 1, warp_n = wid >> 1;
    const int t0 = blockIdx.x * 128;
    const int m0 = blockIdx.y * 128;

    // fill indexing: 256 threads, row = tid>>1 (0..127), half h = tid&1
    const int frow = tid >> 1, fh = tid & 1;
    const __nv_bfloat16* gA_h = Ah + (size_t)(t0 + frow) * K + fh * 8;
    const __nv_bfloat16* gA_l = Al + (size_t)(t0 + frow) * K + fh * 8;
    const __nv_bfloat16* gW_h = g_wh + (size_t)(m0 + frow) * K + fh * 8;
    const __nv_bfloat16* gW_l = g_wl + (size_t)(m0 + frow) * K + fh * 8;
    const uint32_t soff = frow * PITCH + fh * 16;

    // frag lane offsets
    const int lr = lane & 7, s = lane >> 3;
    const uint32_t aoff = sb + (uint32_t)(warp_m * 64 + lr + (s & 1) * 8) * PITCH + (s >> 1) * 16;
    const uint32_t woff = sb + 12288u + (uint32_t)(warp_n * 32 + lr + (s >> 1) * 8) * PITCH + (s & 1) * 16;

    float acc[4][4][4] = {};
    const int nc = K >> 4;

    // prologue fill buf 0 (k0 = 0)
    {
        uint4 a = *(const uint4*)gA_h;
        uint4 b = *(const uint4*)gA_l;
        uint4 c = *(const uint4*)gW_h;
        uint4 d = *(const uint4*)gW_l;
        *(uint4*)(smem + soff)          = a;
        *(uint4*)(smem + 6144 + soff)   = b;
        *(uint4*)(smem + 12288 + soff)  = c;
        *(uint4*)(smem + 18432 + soff)  = d;
    }
    __syncthreads();

    for (int c = 0; c < nc; c++) {
        const uint32_t bb = (c & 1) * BUFSZ;
        uint4 pa, pb, pc, pd;
        if (c + 1 < nc) {
            const int kn = (c + 1) << 4;
            pa = *(const uint4*)(gA_h + kn);
            pb = *(const uint4*)(gA_l + kn);
            pc = *(const uint4*)(gW_h + kn);
            pd = *(const uint4*)(gW_l + kn);
        }
        uint32_t ah[4][4], al[4][4], wh[4][2], wl[4][2];
#pragma unroll
        for (int mt = 0; mt < 4; mt++) {
            LDM4(ah[mt], aoff + bb + mt * (16 * PITCH));
            LDM4(al[mt], aoff + bb + 6144 + mt * (16 * PITCH));
        }
#pragma unroll
        for (int p = 0; p < 2; p++) {
            uint32_t r[4];
            LDM4(r, woff + bb + p * (16 * PITCH));
            wh[2 * p][0] = r[0]; wh[2 * p][1] = r[1];
            wh[2 * p + 1][0] = r[2]; wh[2 * p + 1][1] = r[3];
            LDM4(r, woff + bb + 6144 + p * (16 * PITCH));
            wl[2 * p][0] = r[0]; wl[2 * p][1] = r[1];
            wl[2 * p + 1][0] = r[2]; wl[2 * p + 1][1] = r[3];
        }
#pragma unroll
        for (int mt = 0; mt < 4; mt++)
#pragma unroll
            for (int nt = 0; nt < 4; nt++) {
                mma_bf16(acc[mt][nt], ah[mt], wh[nt]);
                mma_bf16(acc[mt][nt], al[mt], wh[nt]);
                mma_bf16(acc[mt][nt], ah[mt], wl[nt]);
            }
        if (c + 1 < nc) {
            const uint32_t nb = ((c + 1) & 1) * BUFSZ;
            *(uint4*)(smem + nb + soff)         = pa;
            *(uint4*)(smem + nb + 6144 + soff)  = pb;
            *(uint4*)(smem + nb + 12288 + soff) = pc;
            *(uint4*)(smem + nb + 18432 + soff) = pd;
        }
        __syncthreads();
    }

    // epilogue
    const int rl = lane >> 2, cl = (lane & 3) * 2;
#pragma unroll
    for (int nt = 0; nt < 4; nt++) {
        const int m = m0 + warp_n * 32 + nt * 8 + cl;
        const float b0 = bias[m], b1 = bias[m + 1];
#pragma unroll
        for (int mt = 0; mt < 4; mt++) {
            const int t = t0 + warp_m * 64 + mt * 16 + rl;
            float v00 = acc[mt][nt][0] + b0, v01 = acc[mt][nt][1] + b1;
            float v10 = acc[mt][nt][2] + b0, v11 = acc[mt][nt][3] + b1;
            if (OM == 0) {
                __nv_bfloat162 h0 = __floats2bfloat162_rn(v00, v01);
                float2 f0 = __bfloat1622float2(h0);
                __nv_bfloat162 l0 = __floats2bfloat162_rn(v00 - f0.x, v01 - f0.y);
                __nv_bfloat162 h1 = __floats2bfloat162_rn(v10, v11);
                float2 f1 = __bfloat1622float2(h1);
                __nv_bfloat162 l1 = __floats2bfloat162_rn(v10 - f1.x, v11 - f1.y);
                *(__nv_bfloat162*)(g_ah + (size_t)t * 512 + m) = h0;
                *(__nv_bfloat162*)(g_al + (size_t)t * 512 + m) = l0;
                *(__nv_bfloat162*)(g_ah + (size_t)(t + 8) * 512 + m) = h1;
                *(__nv_bfloat162*)(g_al + (size_t)(t + 8) * 512 + m) = l1;
            } else if (OM == 1) {
                out[(size_t)t * 512 + m] = v00;
                out[(size_t)t * 512 + m + 1] = v01;
                out[(size_t)(t + 8) * 512 + m] = v10;
                out[(size_t)(t + 8) * 512 + m + 1] = v11;
            } else {
                int b = t / 9, hw = t - b * 9;
                out[((size_t)b * 512 + m) * 9 + hw] = v00;
                out[((size_t)b * 512 + m + 1) * 9 + hw] = v01;
                int b2 = (t + 8) / 9, hw2 = (t + 8) - b2 * 9;
                out[((size_t)b2 * 512 + m) * 9 + hw2] = v10;
                out[((size_t)b2 * 512 + m + 1) * 9 + hw2] = v11;
            }
        }
    }
}

// ---------------------------------------------------------------------------
// attention: block per (batch, head); token-major fp32 q/k/v in g_qkv
__global__ void attn_kernel(const float* __restrict__ relh,
                            const float* __restrict__ relw, int colOff) {
    int b = blockIdx.x >> 2;
    int h = blockIdx.x & 3;
    int d = threadIdx.x;  // 0..127
    __shared__ float sq[128][9], sk[128][9], sv[128][9], sp[128][9];
    __shared__ float sl[9][9];
    size_t tb = (size_t)b * 9;
    int ch = h * 128 + d;
    const float* qp = g_qkv + tb * 512 + ch;
    const float* kp = qp + (size_t)T_TOK * 512;
    const float* vp = kp + (size_t)T_TOK * 512;
#pragma unroll
    for (int n = 0; n < 9; n++) {
        sq[d][n] = qp[n * 512];
        sk[d][n] = kp[n * 512];
        sv[d][n] = vp[n * 512];
    }
    float rw[3], rh2[3];
#pragma unroll
    for (int i = 0; i < 3; i++) { rw[i] = relw[ch * 3 + i]; rh2[i] = relh[ch * 3 + i]; }
#pragma unroll
    for (int i = 0; i < 3; i++)
#pragma unroll
        for (int j = 0; j < 3; j++)
            sp[d][i * 3 + j] = rw[i] + rh2[j];
    __syncthreads();
    if (d < 81) {
        int n = d / 9, mm = d % 9;
        float a = 0.f;
#pragma unroll 4
        for (int dd = 0; dd < 128; dd++)
            a += sq[dd][n] * sk[dd][mm] + sp[dd][n] * sq[dd][mm];
        sl[n][mm] = a;
    }
    __syncthreads();
    if (d < 9) {
        float mx = sl[d][0];
#pragma unroll
        for (int mm = 1; mm < 9; mm++) mx = fmaxf(mx, sl[d][mm]);
        float e[9], sum = 0.f;
#pragma unroll
        for (int mm = 0; mm < 9; mm++) { e[mm] = __expf(sl[d][mm] - mx); sum += e[mm]; }
        float inv = 1.f / sum;
#pragma unroll
        for (int mm = 0; mm < 9; mm++) sl[d][mm] = e[mm] * inv;
    }
    __syncthreads();
    float* op = g_big + tb * 1536 + colOff + ch;
#pragma unroll
    for (int n = 0; n < 9; n++) {
        float a = 0.f;
#pragma unroll
        for (int mm = 0; mm < 9; mm++) a = fmaf(sv[d][mm], sl[n][mm], a);
        op[(size_t)n * 1536] = a;
    }
}

// ---------------------------------------------------------------------------
extern "C" void kernel_launch(void* const* d_in, const int* in_sizes, int n_in,
                              void* d_out, int out_size) {
    const float* x     = (const float*)d_in[0];
    const float* bn1_g = (const float*)d_in[1];
    const float* bn1_b = (const float*)d_in[2];
    const float* w1    = (const float*)d_in[3];
    const float* b1    = (const float*)d_in[4];
    const float* q_w   = (const float*)d_in[5];
    const float* q_b   = (const float*)d_in[6];
    const float* k_w   = (const float*)d_in[7];
    const float* k_b   = (const float*)d_in[8];
    const float* v_w   = (const float*)d_in[9];
    const float* v_b   = (const float*)d_in[10];
    const float* rel_h = (const float*)d_in[11];
    const float* rel_w = (const float*)d_in[12];
    const float* bn2_g = (const float*)d_in[13];
    const float* bn2_b = (const float*)d_in[14];
    const float* w2    = (const float*)d_in[15];
    const float* b2    = (const float*)d_in[16];
    const float* bn3_g = (const float*)d_in[17];
    const float* bn3_b = (const float*)d_in[18];
    const float* w3    = (const float*)d_in[19];
    const float* b3    = (const float*)d_in[20];

    __nv_bfloat16 *bh, *bl, *ah, *al;
    float *qkv;
    cudaGetSymbolAddress((void**)&bh, g_bh);
    cudaGetSymbolAddress((void**)&bl, g_bl);
    cudaGetSymbolAddress((void**)&ah, g_ah);
    cudaGetSymbolAddress((void**)&al, g_al);
    cudaGetSymbolAddress((void**)&qkv, g_qkv);

    const int SMB = 2 * BUFSZ;  // 49152
    cudaFuncSetAttribute(mma_gemm<0>, cudaFuncAttributeMaxDynamicSharedMemorySize, SMB);
    cudaFuncSetAttribute(mma_gemm<1>, cudaFuncAttributeMaxDynamicSharedMemorySize, SMB);
    cudaFuncSetAttribute(mma_gemm<2>, cudaFuncAttributeMaxDynamicSharedMemorySize, SMB);

    dim3 gg(T_TOK / 128, 4);  // 288 x 4

    transpose_in<<<4096, 512>>>(x);

    // ---- stage 1 ----
    stats_part<<<64, 512>>>(0);
    stats_fin<<<2, 256>>>(0);
    scaleshift<<<2, 256>>>(bn1_g, bn1_b, 512);
    conv_big<<<9216, 256>>>(512);
    conv_w<<<128, 256>>>(w1);
    mma_gemm<0><<<gg, 256, SMB>>>(bh, bl, 512, b1, nullptr);          // o3 -> g_ah/g_al
    conv_w<<<128, 256>>>(q_w);
    mma_gemm<1><<<gg, 256, SMB>>>(ah, al, 512, q_b, qkv);
    conv_w<<<128, 256>>>(k_w);
    mma_gemm<1><<<gg, 256, SMB>>>(ah, al, 512, k_b, qkv + (size_t)T_TOK * 512);
    conv_w<<<128, 256>>>(v_w);
    mma_gemm<1><<<gg, 256, SMB>>>(ah, al, 512, v_b, qkv + (size_t)2 * T_TOK * 512);
    attn_kernel<<<4096 * 4, 128>>>(rel_h, rel_w, 512);

    // ---- stage 2 ----
    stats_part<<<64, 512>>>(512);
    stats_fin<<<2, 256>>>(512);
    scaleshift<<<4, 256>>>(bn2_g, bn2_b, 1024);
    conv_big<<<18432, 256>>>(1024);
    conv_w<<<256, 256>>>(w2);
    mma_gemm<0><<<gg, 256, SMB>>>(bh, bl, 1024, b2, nullptr);         // o7 -> g_ah/g_al
    conv_w<<<128, 256>>>(q_w);
    mma_gemm<1><<<gg, 256, SMB>>>(ah, al, 512, q_b, qkv);
    conv_w<<<128, 256>>>(k_w);
    mma_gemm<1><<<gg, 256, SMB>>>(ah, al, 512, k_b, qkv + (size_t)T_TOK * 512);
    conv_w<<<128, 256>>>(v_w);
    mma_gemm<1><<<gg, 256, SMB>>>(ah, al, 512, v_b, qkv + (size_t)2 * T_TOK * 512);
    attn_kernel<<<4096 * 4, 128>>>(rel_h, rel_w, 1024);

    // ---- stage 3 ----
    stats_part<<<64, 512>>>(1024);
    stats_fin<<<2, 256>>>(1024);
    scaleshift<<<6, 256>>>(bn3_g, bn3_b, 1536);
    conv_big<<<27648, 256>>>(1536);
    conv_w<<<384, 256>>>(w3);
    mma_gemm<2><<<gg, 256, SMB>>>(bh, bl, 1536, b3, (float*)d_out);
}

// round 5
// speedup vs baseline: 3.4135x; 1.0771x over previous
#include <cuda_runtime.h>
#include <cuda_bf16.h>
#include <cstdint>

#define T_TOK 36864

// ---------------- scratch ----------------
__device__ __align__(16) float g_big[56623104];            // [T][1536] fp32: x | o3_att | o7_att
__device__ __align__(16) float g_qkv[56623104];            // [T][1536] fp32: q | k | v
__device__ __align__(16) __nv_bfloat16 g_bh[56623104];     // BN'd stage input hi [T][Ks]
__device__ __align__(16) __nv_bfloat16 g_bl[56623104];     // lo
__device__ __align__(16) __nv_bfloat16 g_ah[18874368];     // o3/o7 hi [T][512]
__device__ __align__(16) __nv_bfloat16 g_al[18874368];     // lo
__device__ __align__(16) __nv_bfloat16 g_whall[2359296];   // w1|qkv|w2|w3 hi
__device__ __align__(16) __nv_bfloat16 g_wlall[2359296];   // lo
__device__ __align__(16) float g_bqkv[1536];
__device__ __align__(16) float g_ps[2097152];
__device__ __align__(16) float g_pq[2097152];
__device__ float g_mean[1536];
__device__ float g_var[1536];

// weight segment offsets in g_w*all
#define OFF_W1   0u
#define OFF_QKV  262144u
#define OFF_W2   1048576u
#define OFF_W3   1572864u

__device__ __forceinline__ uint32_t smem_u32(const void* p) {
    uint32_t a;
    asm("{ .reg .u64 t; cvta.to.shared.u64 t, %1; cvt.u32.u64 %0, t; }" : "=r"(a) : "l"(p));
    return a;
}
#define LDM4(r, addr)                                                              \
    asm volatile("ldmatrix.sync.aligned.m8n8.x4.shared.b16 {%0,%1,%2,%3}, [%4];"   \
        : "=r"((r)[0]), "=r"((r)[1]), "=r"((r)[2]), "=r"((r)[3]) : "r"(addr))
#define CPA(d, s)   asm volatile("cp.async.cg.shared.global [%0], [%1], 16;" :: "r"(d), "l"(s))
#define CPCOMMIT()  asm volatile("cp.async.commit_group;" ::: "memory")
#define CPWAIT0()   asm volatile("cp.async.wait_group 0;" ::: "memory")

__device__ __forceinline__ void mma_bf16(float* c, const uint32_t* a, const uint32_t* b) {
    asm volatile("mma.sync.aligned.m16n8k16.row.col.f32.bf16.bf16.f32 "
        "{%0,%1,%2,%3}, {%4,%5,%6,%7}, {%8,%9}, {%0,%1,%2,%3};"
        : "+f"(c[0]), "+f"(c[1]), "+f"(c[2]), "+f"(c[3])
        : "r"(a[0]), "r"(a[1]), "r"(a[2]), "r"(a[3]), "r"(b[0]), "r"(b[1]));
}

__device__ __forceinline__ void split8_store(float* v, __nv_bfloat16* dh, __nv_bfloat16* dl) {
    uint4 H, L;
    uint32_t* hp = &H.x;
    uint32_t* lp = &L.x;
#pragma unroll
    for (int i = 0; i < 4; i++) {
        __nv_bfloat162 h = __floats2bfloat162_rn(v[2 * i], v[2 * i + 1]);
        float2 hf = __bfloat1622float2(h);
        __nv_bfloat162 l = __floats2bfloat162_rn(v[2 * i] - hf.x, v[2 * i + 1] - hf.y);
        hp[i] = *(uint32_t*)&h;
        lp[i] = *(uint32_t*)&l;
    }
    *(uint4*)dh = H;
    *(uint4*)dl = L;
}

// ---------------------------------------------------------------------------
// prep: blocks [0,4096): transpose x into g_big cols 0-511 + per-batch stats
//       blocks [4096,4672): split all weights fp32 -> bf16 hi/lo
//       blocks [4672,4675): concat q/k/v bias
__global__ void prep(const float* __restrict__ x,
                     const float* __restrict__ w1, const float* __restrict__ qw,
                     const float* __restrict__ kw, const float* __restrict__ vw,
                     const float* __restrict__ w2, const float* __restrict__ w3,
                     const float* __restrict__ qb, const float* __restrict__ kb,
                     const float* __restrict__ vb) {
    const int blk = blockIdx.x, tid = threadIdx.x;
    if (blk < 4096) {
        __shared__ float s[4608];
        const float* xp = x + (size_t)blk * 4608;
#pragma unroll
        for (int i = tid; i < 4608; i += 512) s[i] = xp[i];
        __syncthreads();
        float sum = 0.f, sq = 0.f;
#pragma unroll
        for (int hw = 0; hw < 9; hw++) {
            float v = s[tid * 9 + hw];
            g_big[((size_t)blk * 9 + hw) * 1536 + tid] = v;
            sum += v;
            sq += v * v;
        }
        g_ps[(size_t)blk * 512 + tid] = sum;
        g_pq[(size_t)blk * 512 + tid] = sq;
    } else if (blk < 4672) {
        uint32_t i8 = (uint32_t)(blk - 4096) * 4096u + (uint32_t)tid * 8u;
        const float* src;
        uint32_t seg;
        if      (i8 <  262144u) { src = w1; seg = 0u; }
        else if (i8 <  524288u) { src = qw; seg = 262144u; }
        else if (i8 <  786432u) { src = kw; seg = 524288u; }
        else if (i8 < 1048576u) { src = vw; seg = 786432u; }
        else if (i8 < 1572864u) { src = w2; seg = 1048576u; }
        else                    { src = w3; seg = 1572864u; }
        const float* p = src + (i8 - seg);
        float v[8];
        *(float4*)v       = *(const float4*)p;
        *(float4*)(v + 4) = *(const float4*)(p + 4);
        split8_store(v, g_whall + i8, g_wlall + i8);
    } else {
        int i = (blk - 4672) * 512 + tid;
        float v;
        if (i < 512) v = qb[i];
        else if (i < 1024) v = kb[i - 512];
        else v = vb[i - 1024];
        g_bqkv[i] = v;
    }
}

// ---------------------------------------------------------------------------
// partial column stats over g_big cols [coff, coff+512)
__global__ void stats_part(int coff) {
    int c = coff + threadIdx.x;
    int r0 = blockIdx.x * 576;
    float s = 0.f, q = 0.f;
    for (int r = r0; r < r0 + 576; r++) {
        float v = g_big[(size_t)r * 1536 + c];
        s += v;
        q += v * v;
    }
    g_ps[(size_t)blockIdx.x * 512 + threadIdx.x] = s;
    g_pq[(size_t)blockIdx.x * 512 + threadIdx.x] = q;
}

// finalize mean/var for 512 channels at coff from nparts partials
__global__ void stats_fin(int coff, int nparts) {
    __shared__ float rs[8][32], rq[8][32];
    int lane = threadIdx.x & 31, rp = threadIdx.x >> 5;
    int j = blockIdx.x * 32 + lane;
    float s = 0.f, q = 0.f;
    for (int r = rp; r < nparts; r += 8) {
        s += g_ps[(size_t)r * 512 + j];
        q += g_pq[(size_t)r * 512 + j];
    }
    rs[rp][lane] = s;
    rq[rp][lane] = q;
    __syncthreads();
    if (rp == 0) {
#pragma unroll
        for (int r = 1; r < 8; r++) { s += rs[r][lane]; q += rq[r][lane]; }
        float m = s / (float)T_TOK;
        g_mean[coff + j] = m;
        g_var[coff + j] = q / (float)T_TOK - m * m;
    }
}

// ---------------------------------------------------------------------------
// relu(bn(g_big[:, 0:Ks])) -> bf16 hi/lo [T][Ks]; scale/shift computed inline
__global__ void conv_big(const float* __restrict__ gam, const float* __restrict__ bet, int Ks) {
    uint32_t i8 = ((uint32_t)blockIdx.x * 256u + threadIdx.x) * 8u;
    uint32_t t = i8 / (uint32_t)Ks, c = i8 % (uint32_t)Ks;
    const float* src = g_big + (size_t)t * 1536 + c;
    float v[8], gm[8], bt[8], mn[8], vr[8], a[8];
    *(float4*)v        = *(const float4*)src;
    *(float4*)(v + 4)  = *(const float4*)(src + 4);
    *(float4*)gm       = *(const float4*)(gam + c);
    *(float4*)(gm + 4) = *(const float4*)(gam + c + 4);
    *(float4*)bt       = *(const float4*)(bet + c);
    *(float4*)(bt + 4) = *(const float4*)(bet + c + 4);
    *(float4*)mn       = *(const float4*)(g_mean + c);
    *(float4*)(mn + 4) = *(const float4*)(g_mean + c + 4);
    *(float4*)vr       = *(const float4*)(g_var + c);
    *(float4*)(vr + 4) = *(const float4*)(g_var + c + 4);
#pragma unroll
    for (int i = 0; i < 8; i++) {
        float sc = gm[i] * rsqrtf(vr[i] + 1e-5f);
        a[i] = fmaxf(fmaf(v[i], sc, bt[i] - mn[i] * sc), 0.f);
    }
    split8_store(a, g_bh + i8, g_bl + i8);
}

// ---------------------------------------------------------------------------
// out[t,m] = sum_k A[t,k]*W[m,k] + bias[m], bf16x3, cp.async 2-stage.
// Block 128 tok x 128 ch, 8 warps (2x4), warp 64x32, k16 chunks, 2 CTA/SM.
// OM: 0 = split-out to g_ah/g_al [T][512]; 1 = fp32 [T][1536]; 2 = fp32 [B,512,3,3]
#define PITCH 48
#define BUFSZ 24576
template<int OM>
__global__ __launch_bounds__(256, 2)
void mma_gemm(const __nv_bfloat16* __restrict__ Ah, const __nv_bfloat16* __restrict__ Al,
              const __nv_bfloat16* __restrict__ Wh, const __nv_bfloat16* __restrict__ Wl,
              const int K, const float* __restrict__ bias, float* __restrict__ out) {
    extern __shared__ char smem[];
    const uint32_t sb = smem_u32(smem);
    const int tid = threadIdx.x;
    const int wid = tid >> 5, lane = tid & 31;
    const int warp_m = wid & 1, warp_n = wid >> 1;
    const int t0 = blockIdx.x * 128;
    const int m0 = blockIdx.y * 128;

    const int frow = tid >> 1, fh = tid & 1;
    const __nv_bfloat16* gA_h = Ah + (size_t)(t0 + frow) * K + fh * 8;
    const __nv_bfloat16* gA_l = Al + (size_t)(t0 + frow) * K + fh * 8;
    const __nv_bfloat16* gW_h = Wh + (size_t)(m0 + frow) * K + fh * 8;
    const __nv_bfloat16* gW_l = Wl + (size_t)(m0 + frow) * K + fh * 8;
    const uint32_t sdst = sb + frow * PITCH + fh * 16;

    const int lr = lane & 7, s = lane >> 3;
    const uint32_t aoff = sb + (uint32_t)(warp_m * 64 + lr + (s & 1) * 8) * PITCH + (s >> 1) * 16;
    const uint32_t woff = sb + 12288u + (uint32_t)(warp_n * 32 + lr + (s >> 1) * 8) * PITCH + (s & 1) * 16;

    float acc[4][4][4] = {};
    const int nc = K >> 4;

    // prologue: fill buf 0
    CPA(sdst,         gA_h);
    CPA(sdst + 6144,  gA_l);
    CPA(sdst + 12288, gW_h);
    CPA(sdst + 18432, gW_l);
    CPCOMMIT();

    for (int c = 0; c < nc; c++) {
        CPWAIT0();
        __syncthreads();
        if (c + 1 < nc) {
            const uint32_t nb = ((c + 1) & 1) * BUFSZ;
            const int kn = (c + 1) << 4;
            CPA(sdst + nb,         gA_h + kn);
            CPA(sdst + nb + 6144,  gA_l + kn);
            CPA(sdst + nb + 12288, gW_h + kn);
            CPA(sdst + nb + 18432, gW_l + kn);
        }
        CPCOMMIT();

        const uint32_t bb = (c & 1) * BUFSZ;
        uint32_t ah[4][4], al[4][4], wh[4][2], wl[4][2];
#pragma unroll
        for (int mt = 0; mt < 4; mt++) {
            LDM4(ah[mt], aoff + bb + mt * (16 * PITCH));
            LDM4(al[mt], aoff + bb + 6144 + mt * (16 * PITCH));
        }
#pragma unroll
        for (int p = 0; p < 2; p++) {
            uint32_t r[4];
            LDM4(r, woff + bb + p * (16 * PITCH));
            wh[2 * p][0] = r[0]; wh[2 * p][1] = r[1];
            wh[2 * p + 1][0] = r[2]; wh[2 * p + 1][1] = r[3];
            LDM4(r, woff + bb + 6144 + p * (16 * PITCH));
            wl[2 * p][0] = r[0]; wl[2 * p][1] = r[1];
            wl[2 * p + 1][0] = r[2]; wl[2 * p + 1][1] = r[3];
        }
#pragma unroll
        for (int mt = 0; mt < 4; mt++)
#pragma unroll
            for (int nt = 0; nt < 4; nt++) {
                mma_bf16(acc[mt][nt], ah[mt], wh[nt]);
                mma_bf16(acc[mt][nt], al[mt], wh[nt]);
                mma_bf16(acc[mt][nt], ah[mt], wl[nt]);
            }
    }

    // epilogue
    const int rl = lane >> 2, cl = (lane & 3) * 2;
#pragma unroll
    for (int nt = 0; nt < 4; nt++) {
        const int m = m0 + warp_n * 32 + nt * 8 + cl;
        const float b0 = bias[m], b1 = bias[m + 1];
#pragma unroll
        for (int mt = 0; mt < 4; mt++) {
            const int t = t0 + warp_m * 64 + mt * 16 + rl;
            float v00 = acc[mt][nt][0] + b0, v01 = acc[mt][nt][1] + b1;
            float v10 = acc[mt][nt][2] + b0, v11 = acc[mt][nt][3] + b1;
            if (OM == 0) {
                __nv_bfloat162 h0 = __floats2bfloat162_rn(v00, v01);
                float2 f0 = __bfloat1622float2(h0);
                __nv_bfloat162 l0 = __floats2bfloat162_rn(v00 - f0.x, v01 - f0.y);
                __nv_bfloat162 h1 = __floats2bfloat162_rn(v10, v11);
                float2 f1 = __bfloat1622float2(h1);
                __nv_bfloat162 l1 = __floats2bfloat162_rn(v10 - f1.x, v11 - f1.y);
                *(__nv_bfloat162*)(g_ah + (size_t)t * 512 + m) = h0;
                *(__nv_bfloat162*)(g_al + (size_t)t * 512 + m) = l0;
                *(__nv_bfloat162*)(g_ah + (size_t)(t + 8) * 512 + m) = h1;
                *(__nv_bfloat162*)(g_al + (size_t)(t + 8) * 512 + m) = l1;
            } else if (OM == 1) {
                out[(size_t)t * 1536 + m] = v00;
                out[(size_t)t * 1536 + m + 1] = v01;
                out[(size_t)(t + 8) * 1536 + m] = v10;
                out[(size_t)(t + 8) * 1536 + m + 1] = v11;
            } else {
                int b = t / 9, hw = t - b * 9;
                out[((size_t)b * 512 + m) * 9 + hw] = v00;
                out[((size_t)b * 512 + m + 1) * 9 + hw] = v01;
                int b2 = (t + 8) / 9, hw2 = (t + 8) - b2 * 9;
                out[((size_t)b2 * 512 + m) * 9 + hw2] = v10;
                out[((size_t)b2 * 512 + m + 1) * 9 + hw2] = v11;
            }
        }
    }
}

// ---------------------------------------------------------------------------
// attention: block per (batch, head); g_qkv fp32 [T][1536] = q|k|v
__global__ void attn_kernel(const float* __restrict__ relh,
                            const float* __restrict__ relw, int colOff) {
    int b = blockIdx.x >> 2;
    int h = blockIdx.x & 3;
    int d = threadIdx.x;  // 0..127
    __shared__ float sq[128][9], sk[128][9], sv[128][9], sp[128][9];
    __shared__ float sl[9][9];
    size_t tb = (size_t)b * 9;
    int ch = h * 128 + d;
    const float* qp = g_qkv + tb * 1536 + ch;
#pragma unroll
    for (int n = 0; n < 9; n++) {
        sq[d][n] = qp[n * 1536];
        sk[d][n] = qp[n * 1536 + 512];
        sv[d][n] = qp[n * 1536 + 1024];
    }
    float rw[3], rh2[3];
#pragma unroll
    for (int i = 0; i < 3; i++) { rw[i] = relw[ch * 3 + i]; rh2[i] = relh[ch * 3 + i]; }
#pragma unroll
    for (int i = 0; i < 3; i++)
#pragma unroll
        for (int j = 0; j < 3; j++)
            sp[d][i * 3 + j] = rw[i] + rh2[j];
    __syncthreads();
    if (d < 81) {
        int n = d / 9, mm = d % 9;
        float a = 0.f;
#pragma unroll 4
        for (int dd = 0; dd < 128; dd++)
            a += sq[dd][n] * sk[dd][mm] + sp[dd][n] * sq[dd][mm];
        sl[n][mm] = a;
    }
    __syncthreads();
    if (d < 9) {
        float mx = sl[d][0];
#pragma unroll
        for (int mm = 1; mm < 9; mm++) mx = fmaxf(mx, sl[d][mm]);
        float e[9], sum = 0.f;
#pragma unroll
        for (int mm = 0; mm < 9; mm++) { e[mm] = __expf(sl[d][mm] - mx); sum += e[mm]; }
        float inv = 1.f / sum;
#pragma unroll
        for (int mm = 0; mm < 9; mm++) sl[d][mm] = e[mm] * inv;
    }
    __syncthreads();
    float* op = g_big + tb * 1536 + colOff + ch;
#pragma unroll
    for (int n = 0; n < 9; n++) {
        float a = 0.f;
#pragma unroll
        for (int mm = 0; mm < 9; mm++) a = fmaf(sv[d][mm], sl[n][mm], a);
        op[(size_t)n * 1536] = a;
    }
}

// ---------------------------------------------------------------------------
extern "C" void kernel_launch(void* const* d_in, const int* in_sizes, int n_in,
                              void* d_out, int out_size) {
    const float* x     = (const float*)d_in[0];
    const float* bn1_g = (const float*)d_in[1];
    const float* bn1_b = (const float*)d_in[2];
    const float* w1    = (const float*)d_in[3];
    const float* b1    = (const float*)d_in[4];
    const float* q_w   = (const float*)d_in[5];
    const float* q_b   = (const float*)d_in[6];
    const float* k_w   = (const float*)d_in[7];
    const float* k_b   = (const float*)d_in[8];
    const float* v_w   = (const float*)d_in[9];
    const float* v_b   = (const float*)d_in[10];
    const float* rel_h = (const float*)d_in[11];
    const float* rel_w = (const float*)d_in[12];
    const float* bn2_g = (const float*)d_in[13];
    const float* bn2_b = (const float*)d_in[14];
    const float* w2    = (const float*)d_in[15];
    const float* b2    = (const float*)d_in[16];
    const float* bn3_g = (const float*)d_in[17];
    const float* bn3_b = (const float*)d_in[18];
    const float* w3    = (const float*)d_in[19];
    const float* b3    = (const float*)d_in[20];

    __nv_bfloat16 *bh, *bl, *ah, *al, *wh, *wl;
    float *qkv, *bqkv;
    cudaGetSymbolAddress((void**)&bh, g_bh);
    cudaGetSymbolAddress((void**)&bl, g_bl);
    cudaGetSymbolAddress((void**)&ah, g_ah);
    cudaGetSymbolAddress((void**)&al, g_al);
    cudaGetSymbolAddress((void**)&wh, g_whall);
    cudaGetSymbolAddress((void**)&wl, g_wlall);
    cudaGetSymbolAddress((void**)&qkv, g_qkv);
    cudaGetSymbolAddress((void**)&bqkv, g_bqkv);

    const int SMB = 2 * BUFSZ;  // 49152
    cudaFuncSetAttribute(mma_gemm<0>, cudaFuncAttributeMaxDynamicSharedMemorySize, SMB);
    cudaFuncSetAttribute(mma_gemm<1>, cudaFuncAttributeMaxDynamicSharedMemorySize, SMB);
    cudaFuncSetAttribute(mma_gemm<2>, cudaFuncAttributeMaxDynamicSharedMemorySize, SMB);

    dim3 g4(288, 4), g12(288, 12);

    // 0: transpose + x stats partials + all weight splits + qkv bias concat
    prep<<<4675, 512>>>(x, w1, q_w, k_w, v_w, w2, w3, q_b, k_b, v_b);
    // 1: finalize stats cols 0-511
    stats_fin<<<16, 256>>>(0, 4096);
    // 2: stage-1 BN+relu+split (Ks=512)
    conv_big<<<9216, 256>>>(bn1_g, bn1_b, 512);
    // 3: o3 GEMM (PROFILED SLOT)
    mma_gemm<0><<<g4, 256, SMB>>>(bh, bl, wh + OFF_W1, wl + OFF_W1, 512, b1, nullptr);
    // 4: fused q|k|v GEMM -> g_qkv [T][1536]
    mma_gemm<1><<<g12, 256, SMB>>>(ah, al, wh + OFF_QKV, wl + OFF_QKV, 512, bqkv, qkv);
    // 5: attention -> g_big cols 512-1023
    attn_kernel<<<16384, 128>>>(rel_h, rel_w, 512);
    // 6-8: stats for o3_att, stage-2 split (Ks=1024)
    stats_part<<<64, 512>>>(512);
    stats_fin<<<16, 256>>>(512, 64);
    conv_big<<<18432, 256>>>(bn2_g, bn2_b, 1024);
    // 9: o7 GEMM
    mma_gemm<0><<<g4, 256, SMB>>>(bh, bl, wh + OFF_W2, wl + OFF_W2, 1024, b2, nullptr);
    // 10: fused q|k|v GEMM (stage 2)
    mma_gemm<1><<<g12, 256, SMB>>>(ah, al, wh + OFF_QKV, wl + OFF_QKV, 512, bqkv, qkv);
    // 11: attention -> g_big cols 1024-1535
    attn_kernel<<<16384, 128>>>(rel_h, rel_w, 1024);
    // 12-14: stats for o7_att, stage-3 split (Ks=1536)
    stats_part<<<64, 512>>>(1024);
    stats_fin<<<16, 256>>>(1024, 64);
    conv_big<<<27648, 256>>>(bn3_g, bn3_b, 1536);
    // 15: final GEMM -> d_out [B,512,3,3]
    mma_gemm<2><<<g4, 256, SMB>>>(bh, bl, wh + OFF_W3, wl + OFF_W3, 1536, b3, (float*)d_out);
}